// round 4
// baseline (speedup 1.0000x reference)
#include <cuda_runtime.h>
#include <cstdint>

// Problem constants
#define B_ 2
#define T_ 2048
#define E_ 1024
#define H_ 16
#define D_ 64
#define BT_ (B_ * T_)

// Scratch (allocation-free: __device__ globals)
__device__ float g_q[(size_t)B_ * H_ * T_ * D_];
__device__ float g_k[(size_t)B_ * H_ * T_ * D_];
__device__ float g_v[(size_t)B_ * H_ * T_ * D_];
__device__ float g_att[(size_t)BT_ * E_];

// fp32 -> tf32 bits, round-to-nearest (keeps GEMM error centered ~3e-4)
__device__ __forceinline__ uint32_t tf32u(float x) {
    uint32_t r;
    asm("cvt.rna.tf32.f32 %0, %1;" : "=r"(r) : "f"(x));
    return r;
}

// Warp MMA: D(16x8,f32) += A(16x8,tf32,row) * B(8x8,tf32,col)
__device__ __forceinline__ void mma_tf32(float* c, const uint32_t* a, const uint32_t* b) {
    asm volatile(
        "mma.sync.aligned.m16n8k8.row.col.f32.tf32.tf32.f32 "
        "{%0,%1,%2,%3}, {%4,%5,%6,%7}, {%8,%9}, {%0,%1,%2,%3};"
        : "+f"(c[0]), "+f"(c[1]), "+f"(c[2]), "+f"(c[3])
        : "r"(a[0]), "r"(a[1]), "r"(a[2]), "r"(a[3]), "r"(b[0]), "r"(b[1]));
}

// ============================================================================
// TF32 mma.sync GEMM:  C[m,n] = sum_k A[m,k] * Bmat[n,k]   (both K-major, "NT")
// BM=BN=128, BK=16. 256 threads = 8 warps (2 in M x 4 in N), warp tile 64x32,
// 4x4 m16n8k8 fragments. Double-buffered smem, register-staged LDG.
// MODE 0: A = x, scatter into g_q/g_k/g_v ([B,H,T,D]).  MODE 1: A=g_att -> C.
// ============================================================================
#define BM 128
#define BN 128
#define BK 16
#define LDP (BK + 4)   // 20 u32: rows 80B (16B-aligned), conflict-free frag LDS

template <int MODE, int Ntot, int Ktot>
__global__ void __launch_bounds__(256) mma_gemm(const float* __restrict__ Ain,
                                                const float* __restrict__ Bmat,
                                                float* __restrict__ C) {
    __shared__ uint32_t As[2][BM][LDP];
    __shared__ uint32_t Bs[2][BN][LDP];

    const float* A = (MODE == 0) ? Ain : g_att;

    const int tid = threadIdx.x;
    const int wid = tid >> 5;
    const int lane = tid & 31;
    const int gid = lane >> 2;   // group id 0..7
    const int tig = lane & 3;    // thread-in-group 0..3
    const int wm = (wid & 1) * 64;   // warp M offset in tile
    const int wn = (wid >> 1) * 32;  // warp N offset in tile
    const int m0 = blockIdx.y * BM;
    const int n0 = blockIdx.x * BN;

    // Global-load indices: 512 float4 per tile, 2 per thread per matrix
    const int r0g = tid >> 2;               // row of first float4
    const int c0g = (tid & 3) << 2;         // col of first float4
    const int r1g = (tid + 256) >> 2;
    const int c1g = ((tid + 256) & 3) << 2;

    float acc[4][4][4];
#pragma unroll
    for (int i = 0; i < 4; i++)
#pragma unroll
        for (int j = 0; j < 4; j++)
#pragma unroll
            for (int v = 0; v < 4; v++) acc[i][j][v] = 0.0f;

    float4 ra0, ra1, rb0, rb1;

#define LDG_TILE(k0)                                                                 \
    do {                                                                             \
        ra0 = *(const float4*)(A + (size_t)(m0 + r0g) * Ktot + (k0) + c0g);          \
        ra1 = *(const float4*)(A + (size_t)(m0 + r1g) * Ktot + (k0) + c1g);          \
        rb0 = *(const float4*)(Bmat + (size_t)(n0 + r0g) * Ktot + (k0) + c0g);       \
        rb1 = *(const float4*)(Bmat + (size_t)(n0 + r1g) * Ktot + (k0) + c1g);       \
    } while (0)

#define STS_TILE(bf)                                                                 \
    do {                                                                             \
        *(uint4*)&As[bf][r0g][c0g] =                                                 \
            make_uint4(tf32u(ra0.x), tf32u(ra0.y), tf32u(ra0.z), tf32u(ra0.w));      \
        *(uint4*)&As[bf][r1g][c1g] =                                                 \
            make_uint4(tf32u(ra1.x), tf32u(ra1.y), tf32u(ra1.z), tf32u(ra1.w));      \
        *(uint4*)&Bs[bf][r0g][c0g] =                                                 \
            make_uint4(tf32u(rb0.x), tf32u(rb0.y), tf32u(rb0.z), tf32u(rb0.w));      \
        *(uint4*)&Bs[bf][r1g][c1g] =                                                 \
            make_uint4(tf32u(rb1.x), tf32u(rb1.y), tf32u(rb1.z), tf32u(rb1.w));      \
    } while (0)

    LDG_TILE(0);
    STS_TILE(0);
    __syncthreads();

    const int NITER = Ktot / BK;
    for (int it = 0; it < NITER; ++it) {
        const int cur = it & 1;
        if (it + 1 < NITER) LDG_TILE((it + 1) * BK);

#pragma unroll
        for (int kc = 0; kc < 2; kc++) {
            uint32_t af[4][4], bf[4][2];
            const int kk = kc * 8 + tig;
#pragma unroll
            for (int mi = 0; mi < 4; mi++) {
                const int r = wm + mi * 16 + gid;
                af[mi][0] = As[cur][r][kk];
                af[mi][1] = As[cur][r + 8][kk];
                af[mi][2] = As[cur][r][kk + 4];
                af[mi][3] = As[cur][r + 8][kk + 4];
            }
#pragma unroll
            for (int ni = 0; ni < 4; ni++) {
                const int cN = wn + ni * 8 + gid;
                bf[ni][0] = Bs[cur][cN][kk];
                bf[ni][1] = Bs[cur][cN][kk + 4];
            }
#pragma unroll
            for (int mi = 0; mi < 4; mi++)
#pragma unroll
                for (int ni = 0; ni < 4; ni++)
                    mma_tf32(acc[mi][ni], af[mi], bf[ni]);
        }

        if (it + 1 < NITER) {
            STS_TILE(cur ^ 1);
            __syncthreads();
        }
    }

    // Epilogue. Thread owns C rows (m, m+8), cols (n, n+1) per fragment.
#pragma unroll
    for (int mi = 0; mi < 4; mi++) {
#pragma unroll
        for (int ni = 0; ni < 4; ni++) {
            const int m = m0 + wm + mi * 16 + gid;
            const int n = n0 + wn + ni * 8 + 2 * tig;
            if (MODE == 0) {
                const int which = n >> 10;       // / E_
                const int e = n & (E_ - 1);
                const int h = e >> 6;
                const int d = e & 63;
                float* base = (which == 0) ? g_q : (which == 1) ? g_k : g_v;
#pragma unroll
                for (int rr = 0; rr < 2; rr++) {
                    const int mm = m + rr * 8;
                    const int b = mm >> 11;          // / T_
                    const int t = mm & (T_ - 1);
                    float2 o = make_float2(acc[mi][ni][2 * rr], acc[mi][ni][2 * rr + 1]);
                    *(float2*)(base + (((size_t)(b * H_ + h) * T_ + t) * D_ + d)) = o;
                }
            } else {
#pragma unroll
                for (int rr = 0; rr < 2; rr++) {
                    const int mm = m + rr * 8;
                    float2 o = make_float2(acc[mi][ni][2 * rr], acc[mi][ni][2 * rr + 1]);
                    *(float2*)(C + (size_t)mm * Ntot + n) = o;
                }
            }
        }
    }
#undef LDG_TILE
#undef STS_TILE
}

// ============================================================================
// Causal flash attention (fp32 SIMT): 1 thread = 1 query row
// ============================================================================
#define QB 128
#define KB 64
#define DP (D_ + 4)

__global__ void __launch_bounds__(128) attn_kernel() {
    __shared__ float Ks[KB][DP];
    __shared__ float Vs[KB][DP];

    const int tid = threadIdx.x;
    const int bh = blockIdx.y;
    const int q0 = blockIdx.x * QB;
    const int r = q0 + tid;

    const float* qptr = g_q + ((size_t)bh * T_ + r) * D_;
    float q[D_];
#pragma unroll
    for (int i = 0; i < D_ / 4; i++) {
        float4 v = *(const float4*)(qptr + 4 * i);
        q[4 * i + 0] = v.x; q[4 * i + 1] = v.y;
        q[4 * i + 2] = v.z; q[4 * i + 3] = v.w;
    }

    float acc[D_];
#pragma unroll
    for (int d = 0; d < D_; d++) acc[d] = 0.0f;
    float mrow = __int_as_float(0xff800000);
    float lrow = 0.0f;
    const float scale = 0.125f;

    const float* kbase = g_k + (size_t)bh * T_ * D_;
    const float* vbase = g_v + (size_t)bh * T_ * D_;

    const int ntiles = (q0 + QB) / KB;
    for (int kt = 0; kt < ntiles; kt++) {
        const int j0 = kt * KB;
#pragma unroll
        for (int i = 0; i < 8; i++) {
            int f4 = tid + i * 128;
            int row = f4 >> 4;
            int col = (f4 & 15) << 2;
            *(float4*)&Ks[row][col] = *(const float4*)(kbase + (size_t)(j0 + row) * D_ + col);
            *(float4*)&Vs[row][col] = *(const float4*)(vbase + (size_t)(j0 + row) * D_ + col);
        }
        __syncthreads();

        int jmax = r - j0 + 1;
        if (jmax > KB) jmax = KB;
        for (int j = 0; j < jmax; j++) {
            const float4* kr = (const float4*)&Ks[j][0];
            float s0 = 0.f, s1 = 0.f, s2 = 0.f, s3 = 0.f;
#pragma unroll
            for (int i = 0; i < 16; i++) {
                float4 kv = kr[i];
                s0 += q[4 * i + 0] * kv.x;
                s1 += q[4 * i + 1] * kv.y;
                s2 += q[4 * i + 2] * kv.z;
                s3 += q[4 * i + 3] * kv.w;
            }
            float s = ((s0 + s1) + (s2 + s3)) * scale;

            if (s > mrow) {
                float corr = __expf(mrow - s);
#pragma unroll
                for (int d = 0; d < D_; d++) acc[d] *= corr;
                lrow *= corr;
                mrow = s;
            }
            float p = __expf(s - mrow);
            lrow += p;

            const float4* vr = (const float4*)&Vs[j][0];
#pragma unroll
            for (int i = 0; i < 16; i++) {
                float4 vv = vr[i];
                acc[4 * i + 0] += p * vv.x;
                acc[4 * i + 1] += p * vv.y;
                acc[4 * i + 2] += p * vv.z;
                acc[4 * i + 3] += p * vv.w;
            }
        }
        __syncthreads();
    }

    const float inv = 1.0f / lrow;
    const int b = bh / H_;
    const int h = bh - b * H_;
    float* optr = g_att + ((size_t)(b * T_ + r)) * E_ + h * D_;
#pragma unroll
    for (int i = 0; i < 16; i++) {
        float4 o;
        o.x = acc[4 * i + 0] * inv;
        o.y = acc[4 * i + 1] * inv;
        o.z = acc[4 * i + 2] * inv;
        o.w = acc[4 * i + 3] * inv;
        *(float4*)(optr + 4 * i) = o;
    }
}

// ============================================================================
// Launch
// ============================================================================
extern "C" void kernel_launch(void* const* d_in, const int* in_sizes, int n_in,
                              void* d_out, int out_size) {
    const float* x = (const float*)d_in[0];       // [B,T,E]
    const float* w_qkv = (const float*)d_in[1];   // [3E,E]
    const float* w_proj = (const float*)d_in[2];  // [E,E]
    float* out = (float*)d_out;                   // [B,T,E]

    // 1) QKV projection (tf32 mma.sync) + scatter into [B,H,T,D] q/k/v
    mma_gemm<0, 3 * E_, E_><<<dim3(3 * E_ / BN, BT_ / BM), 256>>>(x, w_qkv, nullptr);

    // 2) Causal flash attention -> g_att [B*T, E]
    attn_kernel<<<dim3(T_ / QB, B_ * H_), 128>>>();

    // 3) Output projection (tf32 mma.sync) -> d_out
    mma_gemm<1, E_, E_><<<dim3(E_ / BN, BT_ / BM), 256>>>(nullptr, w_proj, out);
}

// round 6
// speedup vs baseline: 3.3263x; 3.3263x over previous
#include <cuda_runtime.h>
#include <cstdint>

// Problem constants
#define B_ 2
#define T_ 2048
#define E_ 1024
#define H_ 16
#define D_ 64
#define BT_ (B_ * T_)

// Scratch (allocation-free: __device__ globals)
__device__ float g_q[(size_t)B_ * H_ * T_ * D_];
__device__ float g_k[(size_t)B_ * H_ * T_ * D_];
__device__ float g_v[(size_t)B_ * H_ * T_ * D_];
__device__ float g_att[(size_t)BT_ * E_];

// fp32 -> tf32 bits, round-to-nearest
__device__ __forceinline__ uint32_t tf32u(float x) {
    uint32_t r;
    asm("cvt.rna.tf32.f32 %0, %1;" : "=r"(r) : "f"(x));
    return r;
}
__device__ __forceinline__ float ex2(float x) {
    float r;
    asm("ex2.approx.f32 %0, %1;" : "=f"(r) : "f"(x));
    return r;
}

// Warp MMA: D(16x8,f32) += A(16x8,tf32,row) * B(8x8,tf32,col)
__device__ __forceinline__ void mma_tf32(float* c, const uint32_t* a, const uint32_t* b) {
    asm volatile(
        "mma.sync.aligned.m16n8k8.row.col.f32.tf32.tf32.f32 "
        "{%0,%1,%2,%3}, {%4,%5,%6,%7}, {%8,%9}, {%0,%1,%2,%3};"
        : "+f"(c[0]), "+f"(c[1]), "+f"(c[2]), "+f"(c[3])
        : "r"(a[0]), "r"(a[1]), "r"(a[2]), "r"(a[3]), "r"(b[0]), "r"(b[1]));
}

// ============================================================================
// TF32 mma.sync GEMM (unchanged from R4):
// C[m,n] = sum_k A[m,k] * Bmat[n,k]  (both K-major).
// ============================================================================
#define BM 128
#define BN 128
#define BK 16
#define LDP (BK + 4)

template <int MODE, int Ntot, int Ktot>
__global__ void __launch_bounds__(256) mma_gemm(const float* __restrict__ Ain,
                                                const float* __restrict__ Bmat,
                                                float* __restrict__ C) {
    __shared__ uint32_t As[2][BM][LDP];
    __shared__ uint32_t Bs[2][BN][LDP];

    const float* A = (MODE == 0) ? Ain : g_att;

    const int tid = threadIdx.x;
    const int wid = tid >> 5;
    const int lane = tid & 31;
    const int gid = lane >> 2;
    const int tig = lane & 3;
    const int wm = (wid & 1) * 64;
    const int wn = (wid >> 1) * 32;
    const int m0 = blockIdx.y * BM;
    const int n0 = blockIdx.x * BN;

    const int r0g = tid >> 2;
    const int c0g = (tid & 3) << 2;
    const int r1g = (tid + 256) >> 2;
    const int c1g = ((tid + 256) & 3) << 2;

    float acc[4][4][4];
#pragma unroll
    for (int i = 0; i < 4; i++)
#pragma unroll
        for (int j = 0; j < 4; j++)
#pragma unroll
            for (int v = 0; v < 4; v++) acc[i][j][v] = 0.0f;

    float4 ra0, ra1, rb0, rb1;

#define LDG_TILE(k0)                                                                 \
    do {                                                                             \
        ra0 = *(const float4*)(A + (size_t)(m0 + r0g) * Ktot + (k0) + c0g);          \
        ra1 = *(const float4*)(A + (size_t)(m0 + r1g) * Ktot + (k0) + c1g);          \
        rb0 = *(const float4*)(Bmat + (size_t)(n0 + r0g) * Ktot + (k0) + c0g);       \
        rb1 = *(const float4*)(Bmat + (size_t)(n0 + r1g) * Ktot + (k0) + c1g);       \
    } while (0)

#define STS_TILE(bf)                                                                 \
    do {                                                                             \
        *(uint4*)&As[bf][r0g][c0g] =                                                 \
            make_uint4(tf32u(ra0.x), tf32u(ra0.y), tf32u(ra0.z), tf32u(ra0.w));      \
        *(uint4*)&As[bf][r1g][c1g] =                                                 \
            make_uint4(tf32u(ra1.x), tf32u(ra1.y), tf32u(ra1.z), tf32u(ra1.w));      \
        *(uint4*)&Bs[bf][r0g][c0g] =                                                 \
            make_uint4(tf32u(rb0.x), tf32u(rb0.y), tf32u(rb0.z), tf32u(rb0.w));      \
        *(uint4*)&Bs[bf][r1g][c1g] =                                                 \
            make_uint4(tf32u(rb1.x), tf32u(rb1.y), tf32u(rb1.z), tf32u(rb1.w));      \
    } while (0)

    LDG_TILE(0);
    STS_TILE(0);
    __syncthreads();

    const int NITER = Ktot / BK;
    for (int it = 0; it < NITER; ++it) {
        const int cur = it & 1;
        if (it + 1 < NITER) LDG_TILE((it + 1) * BK);

#pragma unroll
        for (int kc = 0; kc < 2; kc++) {
            uint32_t af[4][4], bfr[4][2];
            const int kk = kc * 8 + tig;
#pragma unroll
            for (int mi = 0; mi < 4; mi++) {
                const int r = wm + mi * 16 + gid;
                af[mi][0] = As[cur][r][kk];
                af[mi][1] = As[cur][r + 8][kk];
                af[mi][2] = As[cur][r][kk + 4];
                af[mi][3] = As[cur][r + 8][kk + 4];
            }
#pragma unroll
            for (int ni = 0; ni < 4; ni++) {
                const int cN = wn + ni * 8 + gid;
                bfr[ni][0] = Bs[cur][cN][kk];
                bfr[ni][1] = Bs[cur][cN][kk + 4];
            }
#pragma unroll
            for (int mi = 0; mi < 4; mi++)
#pragma unroll
                for (int ni = 0; ni < 4; ni++)
                    mma_tf32(acc[mi][ni], af[mi], bfr[ni]);
        }

        if (it + 1 < NITER) {
            STS_TILE(cur ^ 1);
            __syncthreads();
        }
    }

#pragma unroll
    for (int mi = 0; mi < 4; mi++) {
#pragma unroll
        for (int ni = 0; ni < 4; ni++) {
            const int m = m0 + wm + mi * 16 + gid;
            const int n = n0 + wn + ni * 8 + 2 * tig;
            if (MODE == 0) {
                const int which = n >> 10;
                const int e = n & (E_ - 1);
                const int h = e >> 6;
                const int d = e & 63;
                float* base = (which == 0) ? g_q : (which == 1) ? g_k : g_v;
#pragma unroll
                for (int rr = 0; rr < 2; rr++) {
                    const int mm = m + rr * 8;
                    const int b = mm >> 11;
                    const int t = mm & (T_ - 1);
                    float2 o = make_float2(acc[mi][ni][2 * rr], acc[mi][ni][2 * rr + 1]);
                    *(float2*)(base + (((size_t)(b * H_ + h) * T_ + t) * D_ + d)) = o;
                }
            } else {
#pragma unroll
                for (int rr = 0; rr < 2; rr++) {
                    const int mm = m + rr * 8;
                    float2 o = make_float2(acc[mi][ni][2 * rr], acc[mi][ni][2 * rr + 1]);
                    *(float2*)(C + (size_t)mm * Ntot + n) = o;
                }
            }
        }
    }
#undef LDG_TILE
#undef STS_TILE
}

// ============================================================================
// TF32 mma.sync causal flash attention.
// Block: 128 q-rows x 1 head, 256 threads (8 warps, 16 rows/warp). K-tile 64.
// smem: Ks[64][68] (K-major tf32), Vt[64][68] (V transposed tf32),
//       P[8 warps][16][68] (per-warp probs, tf32).
// ============================================================================
#define ASTR 68
#define AQB 128
#define AKB 64
// scale * log2(e):  (1/8) * 1.4426950408889634
#define SCL2E 0.18033688011112042f
#define ASMEM ((2 * 64 * ASTR + 8 * 16 * ASTR) * 4)

__global__ void __launch_bounds__(256) attn_mma() {
    extern __shared__ uint32_t sm[];
    uint32_t* Ks = sm;                        // [64][ASTR]
    uint32_t* Vt = sm + 64 * ASTR;            // [64][ASTR]  Vt[d][j] = V[j][d]
    const int tid = threadIdx.x;
    const int wid = tid >> 5;
    const int lane = tid & 31;
    const int gid = lane >> 2;
    const int tig = lane & 3;
    uint32_t* Pw = sm + 2 * 64 * ASTR + wid * (16 * ASTR);

    const int bh = blockIdx.y;
    const int q0 = blockIdx.x * AQB;
    const int wq = wid * 16;
    const int r1 = q0 + wq + gid;       // first owned row
    const int r2 = r1 + 8;              // second owned row

    const float* kbase = g_k + (size_t)bh * T_ * D_;
    const float* vbase = g_v + (size_t)bh * T_ * D_;

    // Q fragments (held for the whole block): qf[kc] covers d = kc*8..+7
    uint32_t qf[8][4];
    {
        const float* q1 = g_q + ((size_t)bh * T_ + r1) * D_;
        const float* q2 = g_q + ((size_t)bh * T_ + r2) * D_;
#pragma unroll
        for (int kc = 0; kc < 8; kc++) {
            qf[kc][0] = tf32u(q1[kc * 8 + tig]);
            qf[kc][1] = tf32u(q2[kc * 8 + tig]);
            qf[kc][2] = tf32u(q1[kc * 8 + tig + 4]);
            qf[kc][3] = tf32u(q2[kc * 8 + tig + 4]);
        }
    }

    float o[8][4];
#pragma unroll
    for (int i = 0; i < 8; i++)
#pragma unroll
        for (int v = 0; v < 4; v++) o[i][v] = 0.0f;
    float m1 = -__int_as_float(0x7f800000) * 0.0f - __int_as_float(0x7f800000); // -inf
    m1 = __int_as_float(0xff800000);
    float m2 = __int_as_float(0xff800000);
    float l1 = 0.0f, l2 = 0.0f;

    const int ntiles = (q0 + AQB) / AKB;
    for (int kt = 0; kt < ntiles; kt++) {
        const int j0 = kt * AKB;

        // ---- cooperative tile loads ----
        // K: coalesced float4, K-major into Ks[j][d]
#pragma unroll
        for (int i = 0; i < 2; i++) {
            int f4 = tid + i * 256;            // 0..511 (64 rows x 8 f4? no: 64*16/4=... )
            // 64 rows x 64 cols = 1024 f4 total -> 4 per thread
            int f4a = f4;
            int j = f4a >> 4;
            int dc = (f4a & 15) << 2;
            float4 kv = *(const float4*)(kbase + (size_t)(j0 + j) * D_ + dc);
            *(uint4*)&Ks[j * ASTR + dc] =
                make_uint4(tf32u(kv.x), tf32u(kv.y), tf32u(kv.z), tf32u(kv.w));
            int f4b = f4 + 512;
            j = f4b >> 4;
            dc = (f4b & 15) << 2;
            kv = *(const float4*)(kbase + (size_t)(j0 + j) * D_ + dc);
            *(uint4*)&Ks[j * ASTR + dc] =
                make_uint4(tf32u(kv.x), tf32u(kv.y), tf32u(kv.z), tf32u(kv.w));
        }
        // V transposed: gather float4 per (j, 4d) with j varying across lanes
#pragma unroll
        for (int i = 0; i < 4; i++) {
            int v4 = tid + i * 256;            // 0..1023
            int j = v4 & 63;
            int dg = v4 >> 6;                  // 0..15
            float4 vv = *(const float4*)(vbase + (size_t)(j0 + j) * D_ + dg * 4);
            Vt[(dg * 4 + 0) * ASTR + j] = tf32u(vv.x);
            Vt[(dg * 4 + 1) * ASTR + j] = tf32u(vv.y);
            Vt[(dg * 4 + 2) * ASTR + j] = tf32u(vv.z);
            Vt[(dg * 4 + 3) * ASTR + j] = tf32u(vv.w);
        }
        __syncthreads();

        if (j0 <= q0 + wq + 15) {   // tile intersects this warp's rows
            // ---- S = Q K^T (scaled to log2 domain) ----
            float s[8][4];
#pragma unroll
            for (int jn = 0; jn < 8; jn++)
#pragma unroll
                for (int v = 0; v < 4; v++) s[jn][v] = 0.0f;
#pragma unroll
            for (int jn = 0; jn < 8; jn++) {
                const uint32_t* kr = &Ks[(jn * 8 + gid) * ASTR];
#pragma unroll
                for (int kc = 0; kc < 8; kc++) {
                    uint32_t b[2];
                    b[0] = kr[kc * 8 + tig];
                    b[1] = kr[kc * 8 + tig + 4];
                    mma_tf32(s[jn], qf[kc], b);
                }
            }

            // scale + causal mask
            const bool masked = (kt >= ntiles - 2);
#pragma unroll
            for (int jn = 0; jn < 8; jn++) {
                s[jn][0] *= SCL2E; s[jn][1] *= SCL2E;
                s[jn][2] *= SCL2E; s[jn][3] *= SCL2E;
                if (masked) {
                    const int c0 = j0 + jn * 8 + 2 * tig;
                    const int c1 = c0 + 1;
                    if (c0 > r1) s[jn][0] = __int_as_float(0xff800000);
                    if (c1 > r1) s[jn][1] = __int_as_float(0xff800000);
                    if (c0 > r2) s[jn][2] = __int_as_float(0xff800000);
                    if (c1 > r2) s[jn][3] = __int_as_float(0xff800000);
                }
            }

            // ---- online softmax ----
            float nm1 = m1, nm2 = m2;
#pragma unroll
            for (int jn = 0; jn < 8; jn++) {
                nm1 = fmaxf(nm1, fmaxf(s[jn][0], s[jn][1]));
                nm2 = fmaxf(nm2, fmaxf(s[jn][2], s[jn][3]));
            }
            nm1 = fmaxf(nm1, __shfl_xor_sync(0xffffffff, nm1, 1));
            nm1 = fmaxf(nm1, __shfl_xor_sync(0xffffffff, nm1, 2));
            nm2 = fmaxf(nm2, __shfl_xor_sync(0xffffffff, nm2, 1));
            nm2 = fmaxf(nm2, __shfl_xor_sync(0xffffffff, nm2, 2));

            const float corr1 = ex2(m1 - nm1);   // exp2(-inf)=0 on first tile
            const float corr2 = ex2(m2 - nm2);
            m1 = nm1; m2 = nm2;

            float ls1 = 0.0f, ls2 = 0.0f;
#pragma unroll
            for (int jn = 0; jn < 8; jn++) {
                float p0 = ex2(s[jn][0] - nm1);
                float p1 = ex2(s[jn][1] - nm1);
                float p2 = ex2(s[jn][2] - nm2);
                float p3 = ex2(s[jn][3] - nm2);
                ls1 += p0 + p1;
                ls2 += p2 + p3;
                const int cw = jn * 8 + 2 * tig;
                *(uint2*)&Pw[gid * ASTR + cw] = make_uint2(tf32u(p0), tf32u(p1));
                *(uint2*)&Pw[(gid + 8) * ASTR + cw] = make_uint2(tf32u(p2), tf32u(p3));
            }
            ls1 += __shfl_xor_sync(0xffffffff, ls1, 1);
            ls1 += __shfl_xor_sync(0xffffffff, ls1, 2);
            ls2 += __shfl_xor_sync(0xffffffff, ls2, 1);
            ls2 += __shfl_xor_sync(0xffffffff, ls2, 2);
            l1 = l1 * corr1 + ls1;
            l2 = l2 * corr2 + ls2;

            // rescale O
#pragma unroll
            for (int dn = 0; dn < 8; dn++) {
                o[dn][0] *= corr1; o[dn][1] *= corr1;
                o[dn][2] *= corr2; o[dn][3] *= corr2;
            }

            __syncwarp();

            // ---- O += P V ----
#pragma unroll
            for (int kc = 0; kc < 8; kc++) {
                uint32_t pf[4];
                pf[0] = Pw[gid * ASTR + kc * 8 + tig];
                pf[1] = Pw[(gid + 8) * ASTR + kc * 8 + tig];
                pf[2] = Pw[gid * ASTR + kc * 8 + tig + 4];
                pf[3] = Pw[(gid + 8) * ASTR + kc * 8 + tig + 4];
#pragma unroll
                for (int dn = 0; dn < 8; dn++) {
                    uint32_t b[2];
                    b[0] = Vt[(dn * 8 + gid) * ASTR + kc * 8 + tig];
                    b[1] = Vt[(dn * 8 + gid) * ASTR + kc * 8 + tig + 4];
                    mma_tf32(o[dn], pf, b);
                }
            }
        }
        __syncthreads();
    }

    // ---- write normalized output, head-reassembled [B*T, E] ----
    const float inv1 = 1.0f / l1;
    const float inv2 = 1.0f / l2;
    const int b = bh / H_;
    const int h = bh - b * H_;
    float* o1 = g_att + ((size_t)(b * T_ + r1)) * E_ + h * D_;
    float* o2 = g_att + ((size_t)(b * T_ + r2)) * E_ + h * D_;
#pragma unroll
    for (int dn = 0; dn < 8; dn++) {
        const int d = dn * 8 + 2 * tig;
        *(float2*)(o1 + d) = make_float2(o[dn][0] * inv1, o[dn][1] * inv1);
        *(float2*)(o2 + d) = make_float2(o[dn][2] * inv2, o[dn][3] * inv2);
    }
}

// ============================================================================
// Launch
// ============================================================================
extern "C" void kernel_launch(void* const* d_in, const int* in_sizes, int n_in,
                              void* d_out, int out_size) {
    const float* x = (const float*)d_in[0];       // [B,T,E]
    const float* w_qkv = (const float*)d_in[1];   // [3E,E]
    const float* w_proj = (const float*)d_in[2];  // [E,E]
    float* out = (float*)d_out;                   // [B,T,E]

    static bool attr_done = false;
    if (!attr_done) {
        cudaFuncSetAttribute(attn_mma, cudaFuncAttributeMaxDynamicSharedMemorySize, ASMEM);
        attr_done = true;
    }

    // 1) QKV projection (tf32 mma.sync) + scatter into [B,H,T,D] q/k/v
    mma_gemm<0, 3 * E_, E_><<<dim3(3 * E_ / BN, BT_ / BM), 256>>>(x, w_qkv, nullptr);

    // 2) Causal flash attention (tf32 mma.sync) -> g_att [B*T, E]
    attn_mma<<<dim3(T_ / AQB, B_ * H_), 256, ASMEM>>>();

    // 3) Output projection (tf32 mma.sync) -> d_out
    mma_gemm<1, E_, E_><<<dim3(E_ / BN, BT_ / BM), 256>>>(nullptr, w_proj, out);
}

// round 7
// speedup vs baseline: 3.5650x; 1.0718x over previous
#include <cuda_runtime.h>
#include <cstdint>

// Problem constants
#define B_ 2
#define T_ 2048
#define E_ 1024
#define H_ 16
#define D_ 64
#define BT_ (B_ * T_)

// Scratch (allocation-free: __device__ globals). All tf32-valued fp32 bits.
__device__ float g_q[(size_t)B_ * H_ * T_ * D_];
__device__ float g_k[(size_t)B_ * H_ * T_ * D_];
__device__ float g_v[(size_t)B_ * H_ * T_ * D_];
__device__ float g_att[(size_t)BT_ * E_];
__device__ float g_xr[(size_t)BT_ * E_];
__device__ float g_wqkvr[(size_t)3 * E_ * E_];
__device__ float g_wprojr[(size_t)E_ * E_];

// ---------------------------------------------------------------------------
__device__ __forceinline__ uint32_t smem_u32(const void* p) {
    uint32_t a;
    asm("{ .reg .u64 t; cvta.to.shared.u64 t, %1; cvt.u32.u64 %0, t; }" : "=r"(a) : "l"(p));
    return a;
}
__device__ __forceinline__ uint32_t tf32u(float x) {
    uint32_t r;
    asm("cvt.rna.tf32.f32 %0, %1;" : "=r"(r) : "f"(x));
    return r;
}
__device__ __forceinline__ float ex2(float x) {
    float r;
    asm("ex2.approx.f32 %0, %1;" : "=f"(r) : "f"(x));
    return r;
}
__device__ __forceinline__ void mma_tf32(float* c, const uint32_t* a, const uint32_t* b) {
    asm volatile(
        "mma.sync.aligned.m16n8k8.row.col.f32.tf32.tf32.f32 "
        "{%0,%1,%2,%3}, {%4,%5,%6,%7}, {%8,%9}, {%0,%1,%2,%3};"
        : "+f"(c[0]), "+f"(c[1]), "+f"(c[2]), "+f"(c[3])
        : "r"(a[0]), "r"(a[1]), "r"(a[2]), "r"(a[3]), "r"(b[0]), "r"(b[1]));
}
__device__ __forceinline__ void ldmx4(uint32_t* r, uint32_t a) {
    asm volatile("ldmatrix.sync.aligned.m8n8.x4.shared.b16 {%0,%1,%2,%3}, [%4];"
                 : "=r"(r[0]), "=r"(r[1]), "=r"(r[2]), "=r"(r[3]) : "r"(a));
}
__device__ __forceinline__ void cpa16(uint32_t s, const void* g) {
    asm volatile("cp.async.cg.shared.global [%0], [%1], 16;" :: "r"(s), "l"(g) : "memory");
}
#define CP_COMMIT() asm volatile("cp.async.commit_group;" ::: "memory")
#define CP_WAIT(n) asm volatile("cp.async.wait_group %0;" :: "n"(n) : "memory")

// ---------------------------------------------------------------------------
// Prep: elementwise fp32 -> tf32-rounded fp32 copy (n divisible by 1024)
// ---------------------------------------------------------------------------
__global__ void __launch_bounds__(256) round_copy(const float* __restrict__ in,
                                                  float* __restrict__ out) {
    const int i = (blockIdx.x * 256 + threadIdx.x) * 4;
    float4 v = *(const float4*)(in + i);
    *(uint4*)(out + i) = make_uint4(tf32u(v.x), tf32u(v.y), tf32u(v.z), tf32u(v.w));
}

// ---------------------------------------------------------------------------
// TF32 mma.sync GEMM with cp.async 3-stage pipeline + ldmatrix fragments.
// C[m,n] = sum_k A[m,k] * Bm[n,k]; A,B pre-rounded tf32 bits.
// BM=BN=128, BK=16, 8 warps (2x4), warp tile 64x32.
// MODE 0: scatter rounded into g_q/g_k/g_v. MODE 1: plain fp32 store to C.
// ---------------------------------------------------------------------------
#define BM 128
#define BN 128
#define BK 16
#define LDP 20                       // u32 row stride (80B, conflict-free)
#define STG_U32 (BM * LDP)           // per-matrix stage size, u32 (2560)
#define STAGE_U32 (2 * STG_U32)      // 5120
#define GSMEM (3 * STAGE_U32 * 4)    // 61440 bytes

template <int MODE, int Ntot, int Ktot>
__global__ void __launch_bounds__(256) mma_gemm(const float* __restrict__ A,
                                                const float* __restrict__ Bm,
                                                float* __restrict__ C) {
    extern __shared__ uint32_t sm[];
    const uint32_t sb = smem_u32(sm);

    const int tid = threadIdx.x;
    const int lane = tid & 31;
    const int wid = tid >> 5;
    const int gid = lane >> 2;
    const int tig = lane & 3;
    const int wm = (wid & 1) * 64;
    const int wn = (wid >> 1) * 32;
    const int m0 = blockIdx.y * BM;
    const int n0 = blockIdx.x * BN;

    const int r0 = tid >> 2;             // 0..63
    const int c0 = (tid & 3) << 2;       // 0,4,8,12

    // Fragment base byte-offsets within a stage (ldmatrix lane mapping)
    const uint32_t aoff = ((wm + (lane & 15)) * LDP + ((lane & 16) >> 2)) * 4;
    const uint32_t boff = ((wn + ((lane & 16) >> 1) + (lane & 7)) * LDP + ((lane & 8) >> 1)) * 4;

    float acc[4][4][4];
#pragma unroll
    for (int i = 0; i < 4; i++)
#pragma unroll
        for (int j = 0; j < 4; j++)
#pragma unroll
            for (int v = 0; v < 4; v++) acc[i][j][v] = 0.0f;

#define ISSUE(g)                                                                      \
    do {                                                                              \
        const int _k0 = (g) * BK;                                                     \
        uint32_t _sa = sb + ((g) % 3) * (STAGE_U32 * 4);                              \
        uint32_t _sbB = _sa + STG_U32 * 4;                                            \
        cpa16(_sa + (r0 * LDP + c0) * 4, A + (size_t)(m0 + r0) * Ktot + _k0 + c0);    \
        cpa16(_sa + ((r0 + 64) * LDP + c0) * 4,                                       \
              A + (size_t)(m0 + r0 + 64) * Ktot + _k0 + c0);                          \
        cpa16(_sbB + (r0 * LDP + c0) * 4, Bm + (size_t)(n0 + r0) * Ktot + _k0 + c0);  \
        cpa16(_sbB + ((r0 + 64) * LDP + c0) * 4,                                      \
              Bm + (size_t)(n0 + r0 + 64) * Ktot + _k0 + c0);                         \
        CP_COMMIT();                                                                  \
    } while (0)

    ISSUE(0);
    ISSUE(1);

    const int NITER = Ktot / BK;
    for (int it = 0; it < NITER; ++it) {
        if (it < NITER - 1) CP_WAIT(1); else CP_WAIT(0);
        __syncthreads();
        if (it + 2 < NITER) ISSUE(it + 2);

        const uint32_t stg = sb + (it % 3) * (STAGE_U32 * 4);
        const uint32_t ab = stg + aoff;
        const uint32_t bb_ = stg + STG_U32 * 4 + boff;

#pragma unroll
        for (int kc = 0; kc < 2; kc++) {
            uint32_t af[4][4], bb[2][4];
#pragma unroll
            for (int mi = 0; mi < 4; mi++)
                ldmx4(af[mi], ab + mi * (16 * LDP * 4) + kc * 32);
#pragma unroll
            for (int p = 0; p < 2; p++)
                ldmx4(bb[p], bb_ + p * (16 * LDP * 4) + kc * 32);
#pragma unroll
            for (int mi = 0; mi < 4; mi++)
#pragma unroll
                for (int ni = 0; ni < 4; ni++)
                    mma_tf32(acc[mi][ni], af[mi], &bb[ni >> 1][(ni & 1) * 2]);
        }
    }
#undef ISSUE

    // Epilogue
#pragma unroll
    for (int mi = 0; mi < 4; mi++) {
#pragma unroll
        for (int ni = 0; ni < 4; ni++) {
            const int m = m0 + wm + mi * 16 + gid;
            const int n = n0 + wn + ni * 8 + 2 * tig;
            if (MODE == 0) {
                const int which = n >> 10;
                const int e = n & (E_ - 1);
                const int h = e >> 6;
                const int d = e & 63;
                float* base = (which == 0) ? g_q : (which == 1) ? g_k : g_v;
#pragma unroll
                for (int rr = 0; rr < 2; rr++) {
                    const int mm = m + rr * 8;
                    const int b = mm >> 11;
                    const int t = mm & (T_ - 1);
                    uint2 o = make_uint2(tf32u(acc[mi][ni][2 * rr]),
                                         tf32u(acc[mi][ni][2 * rr + 1]));
                    *(uint2*)((uint32_t*)base + (((size_t)(b * H_ + h) * T_ + t) * D_ + d)) = o;
                }
            } else {
#pragma unroll
                for (int rr = 0; rr < 2; rr++) {
                    const int mm = m + rr * 8;
                    *(float2*)(C + (size_t)mm * Ntot + n) =
                        make_float2(acc[mi][ni][2 * rr], acc[mi][ni][2 * rr + 1]);
                }
            }
        }
    }
}

// ---------------------------------------------------------------------------
// TF32 mma.sync causal flash attention with ldmatrix fragments.
// Block: 128 q-rows x 1 head, 8 warps x 16 rows. K-tile 64.
// q/k/v pre-rounded tf32 bits; output stored rounded for the proj GEMM.
// ---------------------------------------------------------------------------
#define ASTR 68
#define AQB 128
#define AKB 64
#define SCL2E 0.18033688011112042f   // (1/8) * log2(e)
#define ASMEM ((2 * 64 * ASTR + 8 * 16 * ASTR) * 4)

__global__ void __launch_bounds__(256) attn_mma() {
    extern __shared__ uint32_t sm[];
    const uint32_t sb = smem_u32(sm);
    uint32_t* Vt = sm + 64 * ASTR;

    const int tid = threadIdx.x;
    const int wid = tid >> 5;
    const int lane = tid & 31;
    const int gid = lane >> 2;
    const int tig = lane & 3;

    const int bh = blockIdx.y;
    const int qb = gridDim.x - 1 - blockIdx.x;   // heavy blocks first
    const int q0 = qb * AQB;
    const int wq = wid * 16;
    const int r1 = q0 + wq + gid;
    const int r2 = r1 + 8;

    const uint32_t Ksb = sb;
    const uint32_t Vtb = sb + 64 * ASTR * 4;
    const uint32_t Pwb = sb + (2 * 64 * ASTR + wid * 16 * ASTR) * 4;

    // ldmatrix fragment byte-offsets
    const uint32_t nkoff = ((((lane & 16) >> 1) + (lane & 7)) * ASTR + ((lane & 8) >> 1)) * 4;
    const uint32_t pfoff = ((lane & 15) * ASTR + ((lane & 16) >> 2)) * 4;

    const uint32_t* kbase = (const uint32_t*)(g_k + (size_t)bh * T_ * D_);
    const uint32_t* vbase = (const uint32_t*)(g_v + (size_t)bh * T_ * D_);

    // Q fragments (pre-rounded bits, held for whole block)
    uint32_t qf[8][4];
    {
        const uint32_t* q1 = (const uint32_t*)(g_q) + ((size_t)bh * T_ + r1) * D_;
        const uint32_t* q2 = (const uint32_t*)(g_q) + ((size_t)bh * T_ + r2) * D_;
#pragma unroll
        for (int kc = 0; kc < 8; kc++) {
            qf[kc][0] = q1[kc * 8 + tig];
            qf[kc][1] = q2[kc * 8 + tig];
            qf[kc][2] = q1[kc * 8 + tig + 4];
            qf[kc][3] = q2[kc * 8 + tig + 4];
        }
    }

    float o[8][4];
#pragma unroll
    for (int i = 0; i < 8; i++)
#pragma unroll
        for (int v = 0; v < 4; v++) o[i][v] = 0.0f;
    float m1 = __int_as_float(0xff800000), m2 = __int_as_float(0xff800000);
    float l1 = 0.0f, l2 = 0.0f;

    const int ntiles = (q0 + AQB) / AKB;
    for (int kt = 0; kt < ntiles; kt++) {
        const int j0 = kt * AKB;

        // K tile via cp.async (straight 16B copies)
#pragma unroll
        for (int i = 0; i < 4; i++) {
            int f4 = tid + i * 256;
            int j = f4 >> 4;
            int dc = (f4 & 15) << 2;
            cpa16(Ksb + (j * ASTR + dc) * 4, kbase + (size_t)(j0 + j) * D_ + dc);
        }
        CP_COMMIT();
        // V transposed (manual, raw bits)
#pragma unroll
        for (int i = 0; i < 4; i++) {
            int v4 = tid + i * 256;
            int j = v4 & 63;
            int dg = v4 >> 6;
            uint4 vv = *(const uint4*)(vbase + (size_t)(j0 + j) * D_ + dg * 4);
            Vt[(dg * 4 + 0) * ASTR + j] = vv.x;
            Vt[(dg * 4 + 1) * ASTR + j] = vv.y;
            Vt[(dg * 4 + 2) * ASTR + j] = vv.z;
            Vt[(dg * 4 + 3) * ASTR + j] = vv.w;
        }
        CP_WAIT(0);
        __syncthreads();

        if (j0 <= q0 + wq + 15) {
            // ---- S = Q K^T ----
            float s[8][4];
#pragma unroll
            for (int jn = 0; jn < 8; jn++)
#pragma unroll
                for (int v = 0; v < 4; v++) s[jn][v] = 0.0f;
#pragma unroll
            for (int kc = 0; kc < 8; kc++) {
                uint32_t bb[4][4];
#pragma unroll
                for (int p = 0; p < 4; p++)
                    ldmx4(bb[p], Ksb + nkoff + p * (16 * ASTR * 4) + kc * 32);
#pragma unroll
                for (int jn = 0; jn < 8; jn++)
                    mma_tf32(s[jn], qf[kc], &bb[jn >> 1][(jn & 1) * 2]);
            }

            // scale + causal mask
            const bool masked = (kt >= ntiles - 2);
#pragma unroll
            for (int jn = 0; jn < 8; jn++) {
                s[jn][0] *= SCL2E; s[jn][1] *= SCL2E;
                s[jn][2] *= SCL2E; s[jn][3] *= SCL2E;
                if (masked) {
                    const int c0m = j0 + jn * 8 + 2 * tig;
                    if (c0m > r1) s[jn][0] = __int_as_float(0xff800000);
                    if (c0m + 1 > r1) s[jn][1] = __int_as_float(0xff800000);
                    if (c0m > r2) s[jn][2] = __int_as_float(0xff800000);
                    if (c0m + 1 > r2) s[jn][3] = __int_as_float(0xff800000);
                }
            }

            // ---- online softmax (log2 domain) ----
            float nm1 = m1, nm2 = m2;
#pragma unroll
            for (int jn = 0; jn < 8; jn++) {
                nm1 = fmaxf(nm1, fmaxf(s[jn][0], s[jn][1]));
                nm2 = fmaxf(nm2, fmaxf(s[jn][2], s[jn][3]));
            }
            nm1 = fmaxf(nm1, __shfl_xor_sync(0xffffffff, nm1, 1));
            nm1 = fmaxf(nm1, __shfl_xor_sync(0xffffffff, nm1, 2));
            nm2 = fmaxf(nm2, __shfl_xor_sync(0xffffffff, nm2, 1));
            nm2 = fmaxf(nm2, __shfl_xor_sync(0xffffffff, nm2, 2));

            const float corr1 = ex2(m1 - nm1);
            const float corr2 = ex2(m2 - nm2);
            m1 = nm1; m2 = nm2;

            float ls1 = 0.0f, ls2 = 0.0f;
            uint32_t* Pw = (uint32_t*)(sm) + (Pwb - sb) / 4;
#pragma unroll
            for (int jn = 0; jn < 8; jn++) {
                float p0 = ex2(s[jn][0] - nm1);
                float p1 = ex2(s[jn][1] - nm1);
                float p2 = ex2(s[jn][2] - nm2);
                float p3 = ex2(s[jn][3] - nm2);
                ls1 += p0 + p1;
                ls2 += p2 + p3;
                const int cw = jn * 8 + 2 * tig;
                *(uint2*)&Pw[gid * ASTR + cw] = make_uint2(tf32u(p0), tf32u(p1));
                *(uint2*)&Pw[(gid + 8) * ASTR + cw] = make_uint2(tf32u(p2), tf32u(p3));
            }
            ls1 += __shfl_xor_sync(0xffffffff, ls1, 1);
            ls1 += __shfl_xor_sync(0xffffffff, ls1, 2);
            ls2 += __shfl_xor_sync(0xffffffff, ls2, 1);
            ls2 += __shfl_xor_sync(0xffffffff, ls2, 2);
            l1 = l1 * corr1 + ls1;
            l2 = l2 * corr2 + ls2;

#pragma unroll
            for (int dn = 0; dn < 8; dn++) {
                o[dn][0] *= corr1; o[dn][1] *= corr1;
                o[dn][2] *= corr2; o[dn][3] *= corr2;
            }
            __syncwarp();

            // ---- O += P V ----
#pragma unroll
            for (int kc = 0; kc < 8; kc++) {
                uint32_t pf[4], vb[4][4];
                ldmx4(pf, Pwb + pfoff + kc * 32);
#pragma unroll
                for (int p = 0; p < 4; p++)
                    ldmx4(vb[p], Vtb + nkoff + p * (16 * ASTR * 4) + kc * 32);
#pragma unroll
                for (int dn = 0; dn < 8; dn++)
                    mma_tf32(o[dn], pf, &vb[dn >> 1][(dn & 1) * 2]);
            }
        }
        __syncthreads();
    }

    // ---- write normalized output (rounded for proj GEMM), [B*T, E] ----
    const float inv1 = 1.0f / l1;
    const float inv2 = 1.0f / l2;
    const int b = bh / H_;
    const int h = bh - b * H_;
    uint32_t* o1 = (uint32_t*)(g_att) + ((size_t)(b * T_ + r1)) * E_ + h * D_;
    uint32_t* o2 = (uint32_t*)(g_att) + ((size_t)(b * T_ + r2)) * E_ + h * D_;
#pragma unroll
    for (int dn = 0; dn < 8; dn++) {
        const int d = dn * 8 + 2 * tig;
        *(uint2*)(o1 + d) = make_uint2(tf32u(o[dn][0] * inv1), tf32u(o[dn][1] * inv1));
        *(uint2*)(o2 + d) = make_uint2(tf32u(o[dn][2] * inv2), tf32u(o[dn][3] * inv2));
    }
}

// ---------------------------------------------------------------------------
// Launch
// ---------------------------------------------------------------------------
extern "C" void kernel_launch(void* const* d_in, const int* in_sizes, int n_in,
                              void* d_out, int out_size) {
    const float* x = (const float*)d_in[0];       // [B,T,E]
    const float* w_qkv = (const float*)d_in[1];   // [3E,E]
    const float* w_proj = (const float*)d_in[2];  // [E,E]
    float* out = (float*)d_out;                   // [B,T,E]

    static bool attr_done = false;
    if (!attr_done) {
        cudaFuncSetAttribute(mma_gemm<0, 3 * E_, E_>,
                             cudaFuncAttributeMaxDynamicSharedMemorySize, GSMEM);
        cudaFuncSetAttribute(mma_gemm<1, E_, E_>,
                             cudaFuncAttributeMaxDynamicSharedMemorySize, GSMEM);
        cudaFuncSetAttribute(attn_mma, cudaFuncAttributeMaxDynamicSharedMemorySize, ASMEM);
        attr_done = true;
    }

    float *xr, *wqkvr, *wprojr;
    cudaGetSymbolAddress((void**)&xr, g_xr);
    cudaGetSymbolAddress((void**)&wqkvr, g_wqkvr);
    cudaGetSymbolAddress((void**)&wprojr, g_wprojr);

    // 0) One-time-per-call rounding prep (tf32 RNA), ~10us total
    round_copy<<<BT_ * E_ / 1024, 256>>>(x, xr);
    round_copy<<<3 * E_ * E_ / 1024, 256>>>(w_qkv, wqkvr);
    round_copy<<<E_ * E_ / 1024, 256>>>(w_proj, wprojr);

    // 1) QKV projection -> rounded q/k/v in [B,H,T,D]
    mma_gemm<0, 3 * E_, E_><<<dim3(3 * E_ / BN, BT_ / BM), 256, GSMEM>>>(xr, wqkvr, nullptr);

    // 2) Causal flash attention -> rounded g_att [B*T, E]
    attn_mma<<<dim3(T_ / AQB, B_ * H_), 256, ASMEM>>>();

    // 3) Output projection -> d_out (fp32)
    float* attp;
    cudaGetSymbolAddress((void**)&attp, g_att);
    mma_gemm<1, E_, E_><<<dim3(E_ / BN, BT_ / BM), 256, GSMEM>>>(attp, wprojr, out);
}

// round 10
// speedup vs baseline: 4.2751x; 1.1992x over previous
#include <cuda_runtime.h>
#include <cstdint>

// Problem constants
#define B_ 2
#define T_ 2048
#define E_ 1024
#define H_ 16
#define D_ 64
#define BT_ (B_ * T_)

// Scratch (allocation-free: __device__ globals). All tf32-valued fp32 bits.
__device__ float g_q[(size_t)B_ * H_ * T_ * D_];
__device__ float g_k[(size_t)B_ * H_ * T_ * D_];
__device__ float g_v[(size_t)B_ * H_ * T_ * D_];
__device__ float g_att[(size_t)BT_ * E_];
__device__ float g_xr[(size_t)BT_ * E_];
__device__ float g_wqkvr[(size_t)3 * E_ * E_];
__device__ float g_wprojr[(size_t)E_ * E_];

// ---------------------------------------------------------------------------
__device__ __forceinline__ uint32_t smem_u32(const void* p) {
    uint32_t a;
    asm("{ .reg .u64 t; cvta.to.shared.u64 t, %1; cvt.u32.u64 %0, t; }" : "=r"(a) : "l"(p));
    return a;
}
__device__ __forceinline__ uint32_t tf32u(float x) {
    uint32_t r;
    asm("cvt.rna.tf32.f32 %0, %1;" : "=r"(r) : "f"(x));
    return r;
}
__device__ __forceinline__ float ex2(float x) {
    float r;
    asm("ex2.approx.f32 %0, %1;" : "=f"(r) : "f"(x));
    return r;
}
__device__ __forceinline__ void mma_tf32(float* c, const uint32_t* a, const uint32_t* b) {
    asm volatile(
        "mma.sync.aligned.m16n8k8.row.col.f32.tf32.tf32.f32 "
        "{%0,%1,%2,%3}, {%4,%5,%6,%7}, {%8,%9}, {%0,%1,%2,%3};"
        : "+f"(c[0]), "+f"(c[1]), "+f"(c[2]), "+f"(c[3])
        : "r"(a[0]), "r"(a[1]), "r"(a[2]), "r"(a[3]), "r"(b[0]), "r"(b[1]));
}
__device__ __forceinline__ void ldmx4(uint32_t* r, uint32_t a) {
    asm volatile("ldmatrix.sync.aligned.m8n8.x4.shared.b16 {%0,%1,%2,%3}, [%4];"
                 : "=r"(r[0]), "=r"(r[1]), "=r"(r[2]), "=r"(r[3]) : "r"(a));
}
__device__ __forceinline__ void cpa16(uint32_t s, const void* g) {
    asm volatile("cp.async.cg.shared.global [%0], [%1], 16;" :: "r"(s), "l"(g) : "memory");
}
#define CP_COMMIT() asm volatile("cp.async.commit_group;" ::: "memory")
#define CP_WAIT(n) asm volatile("cp.async.wait_group %0;" :: "n"(n) : "memory")

// ---------------------------------------------------------------------------
// Prep: one kernel rounds x, w_qkv, w_proj to tf32 (RNA). f4 segments:
// x: [0, 1048576), wqkv: [1048576, 1835008), wproj: [1835008, 2097152)
// ---------------------------------------------------------------------------
__global__ void __launch_bounds__(256) round_all(const float* __restrict__ x,
                                                 const float* __restrict__ wq,
                                                 const float* __restrict__ wp) {
    const size_t f4 = (size_t)blockIdx.x * 256 + threadIdx.x;
    const float* src;
    float* dst;
    size_t off;
    if (f4 < 1048576) { src = x; dst = g_xr; off = f4; }
    else if (f4 < 1835008) { src = wq; dst = g_wqkvr; off = f4 - 1048576; }
    else { src = wp; dst = g_wprojr; off = f4 - 1835008; }
    const size_t i = off * 4;
    float4 v = *(const float4*)(src + i);
    *(uint4*)(dst + i) = make_uint4(tf32u(v.x), tf32u(v.y), tf32u(v.z), tf32u(v.w));
}

// ---------------------------------------------------------------------------
// TF32 mma.sync GEMM. 128 threads = 4 warps (2x2), warp tile 64x64.
// BM=BN=128, BK=32, 2-stage cp.async pipeline, ldmatrix fragments.
// C[m,n] = sum_k A[m,k] * Bm[n,k]; A,B pre-rounded tf32 bits.
// MODE 0: scatter rounded into g_q/g_k/g_v. MODE 1: fp32 store to C.
// ---------------------------------------------------------------------------
#define BM 128
#define BN 128
#define BK 32
#define LDPG 36                       // u32 row stride (144B), conflict-free
#define STG_U32 (BM * LDPG)           // 4608
#define STAGE_U32 (2 * STG_U32)       // 9216
#define GSMEM (2 * STAGE_U32 * 4)     // 73728 bytes

template <int MODE, int Ntot, int Ktot>
__global__ void __launch_bounds__(128) mma_gemm(const float* __restrict__ A,
                                                const float* __restrict__ Bm,
                                                float* __restrict__ C) {
    extern __shared__ uint32_t sm[];
    const uint32_t sb = smem_u32(sm);

    const int tid = threadIdx.x;
    const int lane = tid & 31;
    const int wid = tid >> 5;
    const int gid = lane >> 2;
    const int tig = lane & 3;
    const int wm = (wid & 1) * 64;
    const int wn = (wid >> 1) * 64;
    const int m0 = blockIdx.y * BM;
    const int n0 = blockIdx.x * BN;

    // Fragment base byte-offsets within a stage (ldmatrix lane mapping)
    const uint32_t aoff = ((wm + (lane & 15)) * LDPG + ((lane & 16) >> 2)) * 4;
    const uint32_t boff = ((wn + ((lane & 16) >> 1) + (lane & 7)) * LDPG + ((lane & 8) >> 1)) * 4;

    float acc[4][8][4];
#pragma unroll
    for (int i = 0; i < 4; i++)
#pragma unroll
        for (int j = 0; j < 8; j++)
#pragma unroll
            for (int v = 0; v < 4; v++) acc[i][j][v] = 0.0f;

    // 16 cp.async per thread per stage: 128 rows x 8 f4 per matrix
#define ISSUE(g)                                                                      \
    do {                                                                              \
        const int _k0 = (g) * BK;                                                     \
        const uint32_t _sa = sb + ((g) & 1) * (STAGE_U32 * 4);                        \
        const uint32_t _sb2 = _sa + STG_U32 * 4;                                      \
        _Pragma("unroll")                                                             \
        for (int _i = 0; _i < 8; _i++) {                                              \
            const int _id = tid + _i * 128;                                           \
            const int _r = _id >> 3;                                                  \
            const int _c = (_id & 7) << 2;                                            \
            cpa16(_sa + (_r * LDPG + _c) * 4, A + (size_t)(m0 + _r) * Ktot + _k0 + _c); \
            cpa16(_sb2 + (_r * LDPG + _c) * 4, Bm + (size_t)(n0 + _r) * Ktot + _k0 + _c); \
        }                                                                             \
        CP_COMMIT();                                                                  \
    } while (0)

    ISSUE(0);

    const int NITER = Ktot / BK;
#pragma unroll 1
    for (int it = 0; it < NITER; ++it) {
        CP_WAIT(0);
        __syncthreads();
        if (it + 1 < NITER) ISSUE(it + 1);

        const uint32_t stg = sb + (it & 1) * (STAGE_U32 * 4);
        const uint32_t ab = stg + aoff;
        const uint32_t bbv = stg + STG_U32 * 4 + boff;

#pragma unroll
        for (int kc = 0; kc < 4; kc++) {
            uint32_t af[4][4], bb[4][4];
#pragma unroll
            for (int mi = 0; mi < 4; mi++)
                ldmx4(af[mi], ab + mi * (16 * LDPG * 4) + kc * 32);
#pragma unroll
            for (int p = 0; p < 4; p++)
                ldmx4(bb[p], bbv + p * (16 * LDPG * 4) + kc * 32);
#pragma unroll
            for (int mi = 0; mi < 4; mi++)
#pragma unroll
                for (int ni = 0; ni < 8; ni++)
                    mma_tf32(acc[mi][ni], af[mi], &bb[ni >> 1][(ni & 1) * 2]);
        }
    }
#undef ISSUE

    // Epilogue
#pragma unroll
    for (int mi = 0; mi < 4; mi++) {
#pragma unroll
        for (int ni = 0; ni < 8; ni++) {
            const int m = m0 + wm + mi * 16 + gid;
            const int n = n0 + wn + ni * 8 + 2 * tig;
            if (MODE == 0) {
                const int which = n >> 10;
                const int e = n & (E_ - 1);
                const int h = e >> 6;
                const int d = e & 63;
                float* base = (which == 0) ? g_q : (which == 1) ? g_k : g_v;
#pragma unroll
                for (int rr = 0; rr < 2; rr++) {
                    const int mm = m + rr * 8;
                    const int b = mm >> 11;
                    const int t = mm & (T_ - 1);
                    uint2 o = make_uint2(tf32u(acc[mi][ni][2 * rr]),
                                         tf32u(acc[mi][ni][2 * rr + 1]));
                    *(uint2*)((uint32_t*)base + (((size_t)(b * H_ + h) * T_ + t) * D_ + d)) = o;
                }
            } else {
#pragma unroll
                for (int rr = 0; rr < 2; rr++) {
                    const int mm = m + rr * 8;
                    *(float2*)(C + (size_t)mm * Ntot + n) =
                        make_float2(acc[mi][ni][2 * rr], acc[mi][ni][2 * rr + 1]);
                }
            }
        }
    }
}

// ---------------------------------------------------------------------------
// TF32 mma.sync causal flash attention, double-buffered tiles.
// Block: 128 q-rows x 1 head, 8 warps x 16 rows. K-tile 64.
// smem: Ks[2][64][68], Vt[2][64][68], P[8][16][68]. One sync per tile.
// ---------------------------------------------------------------------------
#define ASTR 68
#define AQB 128
#define AKB 64
#define SCL2E 0.18033688011112042f   // (1/8) * log2(e)
#define ASMEM ((4 * 64 * ASTR + 8 * 16 * ASTR) * 4)

__global__ void __launch_bounds__(256) attn_mma() {
    extern __shared__ uint32_t sm[];
    const uint32_t sb = smem_u32(sm);

    const int tid = threadIdx.x;
    const int wid = tid >> 5;
    const int lane = tid & 31;
    const int gid = lane >> 2;
    const int tig = lane & 3;

    const int bh = blockIdx.y;
    const int qb = gridDim.x - 1 - blockIdx.x;   // heavy blocks first
    const int q0 = qb * AQB;
    const int wq = wid * 16;
    const int r1 = q0 + wq + gid;
    const int r2 = r1 + 8;

    const uint32_t Pwb = sb + (4 * 64 * ASTR + wid * 16 * ASTR) * 4;

    // ldmatrix fragment byte-offsets (within a K/Vt buffer)
    const uint32_t nkoff = ((((lane & 16) >> 1) + (lane & 7)) * ASTR + ((lane & 8) >> 1)) * 4;
    const uint32_t pfoff = ((lane & 15) * ASTR + ((lane & 16) >> 2)) * 4;

    const uint32_t* kbase = (const uint32_t*)(g_k + (size_t)bh * T_ * D_);
    const uint32_t* vbase = (const uint32_t*)(g_v + (size_t)bh * T_ * D_);

    // Q fragments (pre-rounded bits, held for whole block)
    uint32_t qf[8][4];
    {
        const uint32_t* q1 = (const uint32_t*)(g_q) + ((size_t)bh * T_ + r1) * D_;
        const uint32_t* q2 = (const uint32_t*)(g_q) + ((size_t)bh * T_ + r2) * D_;
#pragma unroll
        for (int kc = 0; kc < 8; kc++) {
            qf[kc][0] = q1[kc * 8 + tig];
            qf[kc][1] = q2[kc * 8 + tig];
            qf[kc][2] = q1[kc * 8 + tig + 4];
            qf[kc][3] = q2[kc * 8 + tig + 4];
        }
    }

    float o[8][4];
#pragma unroll
    for (int i = 0; i < 8; i++)
#pragma unroll
        for (int v = 0; v < 4; v++) o[i][v] = 0.0f;
    float m1 = __int_as_float(0xff800000), m2 = __int_as_float(0xff800000);
    float l1 = 0.0f, l2 = 0.0f;

#define LOADK(kt, buf)                                                                \
    do {                                                                              \
        const int _j0 = (kt) * AKB;                                                   \
        const uint32_t _kb = sb + (buf) * (64 * ASTR * 4);                            \
        _Pragma("unroll")                                                             \
        for (int _i = 0; _i < 4; _i++) {                                              \
            const int _f4 = tid + _i * 256;                                           \
            const int _j = _f4 >> 4;                                                  \
            const int _dc = (_f4 & 15) << 2;                                          \
            cpa16(_kb + (_j * ASTR + _dc) * 4, kbase + (size_t)(_j0 + _j) * D_ + _dc); \
        }                                                                             \
        CP_COMMIT();                                                                  \
    } while (0)

    // Prologue: tile 0
    LOADK(0, 0);
    {
        uint32_t* Vt = sm + 2 * 64 * ASTR;   // buf 0
#pragma unroll
        for (int i = 0; i < 4; i++) {
            const int v4 = tid + i * 256;
            const int j = v4 & 63;
            const int dg = v4 >> 6;
            uint4 vv = *(const uint4*)(vbase + (size_t)j * D_ + dg * 4);
            Vt[(dg * 4 + 0) * ASTR + j] = vv.x;
            Vt[(dg * 4 + 1) * ASTR + j] = vv.y;
            Vt[(dg * 4 + 2) * ASTR + j] = vv.z;
            Vt[(dg * 4 + 3) * ASTR + j] = vv.w;
        }
    }

    const int ntiles = (q0 + AQB) / AKB;
#pragma unroll 1
    for (int kt = 0; kt < ntiles; kt++) {
        const int j0 = kt * AKB;
        const int buf = kt & 1;

        // Prefetch next tile's V into registers (overlaps the K wait)
        uint4 vr[4];
        if (kt + 1 < ntiles) {
#pragma unroll
            for (int i = 0; i < 4; i++) {
                const int v4 = tid + i * 256;
                const int j = v4 & 63;
                const int dg = v4 >> 6;
                vr[i] = *(const uint4*)(vbase + (size_t)(j0 + AKB + j) * D_ + dg * 4);
            }
        }

        CP_WAIT(0);          // K(kt) landed
        __syncthreads();     // everyone done with buffers of tile kt-1

        if (kt + 1 < ntiles) {
            LOADK(kt + 1, buf ^ 1);
            uint32_t* Vt = sm + (2 + (buf ^ 1)) * 64 * ASTR;
#pragma unroll
            for (int i = 0; i < 4; i++) {
                const int v4 = tid + i * 256;
                const int j = v4 & 63;
                const int dg = v4 >> 6;
                Vt[(dg * 4 + 0) * ASTR + j] = vr[i].x;
                Vt[(dg * 4 + 1) * ASTR + j] = vr[i].y;
                Vt[(dg * 4 + 2) * ASTR + j] = vr[i].z;
                Vt[(dg * 4 + 3) * ASTR + j] = vr[i].w;
            }
        }

        if (j0 <= q0 + wq + 15) {
            const uint32_t Ksb = sb + buf * (64 * ASTR * 4);
            const uint32_t Vtb = sb + (2 + buf) * (64 * ASTR * 4);

            // ---- S = Q K^T ----
            float s[8][4];
#pragma unroll
            for (int jn = 0; jn < 8; jn++)
#pragma unroll
                for (int v = 0; v < 4; v++) s[jn][v] = 0.0f;
#pragma unroll
            for (int kc = 0; kc < 8; kc++) {
                uint32_t bb[4][4];
#pragma unroll
                for (int p = 0; p < 4; p++)
                    ldmx4(bb[p], Ksb + nkoff + p * (16 * ASTR * 4) + kc * 32);
#pragma unroll
                for (int jn = 0; jn < 8; jn++)
                    mma_tf32(s[jn], qf[kc], &bb[jn >> 1][(jn & 1) * 2]);
            }

            // scale + causal mask
            const bool masked = (kt >= ntiles - 2);
#pragma unroll
            for (int jn = 0; jn < 8; jn++) {
                s[jn][0] *= SCL2E; s[jn][1] *= SCL2E;
                s[jn][2] *= SCL2E; s[jn][3] *= SCL2E;
                if (masked) {
                    const int c0m = j0 + jn * 8 + 2 * tig;
                    if (c0m > r1) s[jn][0] = __int_as_float(0xff800000);
                    if (c0m + 1 > r1) s[jn][1] = __int_as_float(0xff800000);
                    if (c0m > r2) s[jn][2] = __int_as_float(0xff800000);
                    if (c0m + 1 > r2) s[jn][3] = __int_as_float(0xff800000);
                }
            }

            // ---- online softmax (log2 domain) ----
            float nm1 = m1, nm2 = m2;
#pragma unroll
            for (int jn = 0; jn < 8; jn++) {
                nm1 = fmaxf(nm1, fmaxf(s[jn][0], s[jn][1]));
                nm2 = fmaxf(nm2, fmaxf(s[jn][2], s[jn][3]));
            }
            nm1 = fmaxf(nm1, __shfl_xor_sync(0xffffffff, nm1, 1));
            nm1 = fmaxf(nm1, __shfl_xor_sync(0xffffffff, nm1, 2));
            nm2 = fmaxf(nm2, __shfl_xor_sync(0xffffffff, nm2, 1));
            nm2 = fmaxf(nm2, __shfl_xor_sync(0xffffffff, nm2, 2));

            const float corr1 = ex2(m1 - nm1);
            const float corr2 = ex2(m2 - nm2);
            m1 = nm1; m2 = nm2;

            float ls1 = 0.0f, ls2 = 0.0f;
            uint32_t* Pw = sm + 4 * 64 * ASTR + wid * 16 * ASTR;
#pragma unroll
            for (int jn = 0; jn < 8; jn++) {
                float p0 = ex2(s[jn][0] - nm1);
                float p1 = ex2(s[jn][1] - nm1);
                float p2 = ex2(s[jn][2] - nm2);
                float p3 = ex2(s[jn][3] - nm2);
                ls1 += p0 + p1;
                ls2 += p2 + p3;
                const int cw = jn * 8 + 2 * tig;
                *(uint2*)&Pw[gid * ASTR + cw] = make_uint2(tf32u(p0), tf32u(p1));
                *(uint2*)&Pw[(gid + 8) * ASTR + cw] = make_uint2(tf32u(p2), tf32u(p3));
            }
            ls1 += __shfl_xor_sync(0xffffffff, ls1, 1);
            ls1 += __shfl_xor_sync(0xffffffff, ls1, 2);
            ls2 += __shfl_xor_sync(0xffffffff, ls2, 1);
            ls2 += __shfl_xor_sync(0xffffffff, ls2, 2);
            l1 = l1 * corr1 + ls1;
            l2 = l2 * corr2 + ls2;

#pragma unroll
            for (int dn = 0; dn < 8; dn++) {
                o[dn][0] *= corr1; o[dn][1] *= corr1;
                o[dn][2] *= corr2; o[dn][3] *= corr2;
            }
            __syncwarp();

            // ---- O += P V ----
#pragma unroll
            for (int kc = 0; kc < 8; kc++) {
                uint32_t pf[4], vb[4][4];
                ldmx4(pf, Pwb + pfoff + kc * 32);
#pragma unroll
                for (int p = 0; p < 4; p++)
                    ldmx4(vb[p], Vtb + nkoff + p * (16 * ASTR * 4) + kc * 32);
#pragma unroll
                for (int dn = 0; dn < 8; dn++)
                    mma_tf32(o[dn], pf, &vb[dn >> 1][(dn & 1) * 2]);
            }
        }
    }
#undef LOADK

    // ---- write normalized output (rounded for proj GEMM), [B*T, E] ----
    const float inv1 = 1.0f / l1;
    const float inv2 = 1.0f / l2;
    const int b = bh / H_;
    const int h = bh - b * H_;
    uint32_t* o1 = (uint32_t*)(g_att) + ((size_t)(b * T_ + r1)) * E_ + h * D_;
    uint32_t* o2 = (uint32_t*)(g_att) + ((size_t)(b * T_ + r2)) * E_ + h * D_;
#pragma unroll
    for (int dn = 0; dn < 8; dn++) {
        const int d = dn * 8 + 2 * tig;
        *(uint2*)(o1 + d) = make_uint2(tf32u(o[dn][0] * inv1), tf32u(o[dn][1] * inv1));
        *(uint2*)(o2 + d) = make_uint2(tf32u(o[dn][2] * inv2), tf32u(o[dn][3] * inv2));
    }
}

// ---------------------------------------------------------------------------
// Launch
// ---------------------------------------------------------------------------
extern "C" void kernel_launch(void* const* d_in, const int* in_sizes, int n_in,
                              void* d_out, int out_size) {
    const float* x = (const float*)d_in[0];       // [B,T,E]
    const float* w_qkv = (const float*)d_in[1];   // [3E,E]
    const float* w_proj = (const float*)d_in[2];  // [E,E]
    float* out = (float*)d_out;                   // [B,T,E]

    static bool attr_done = false;
    if (!attr_done) {
        cudaFuncSetAttribute(mma_gemm<0, 3 * E_, E_>,
                             cudaFuncAttributeMaxDynamicSharedMemorySize, GSMEM);
        cudaFuncSetAttribute(mma_gemm<1, E_, E_>,
                             cudaFuncAttributeMaxDynamicSharedMemorySize, GSMEM);
        cudaFuncSetAttribute(attn_mma, cudaFuncAttributeMaxDynamicSharedMemorySize, ASMEM);
        attr_done = true;
    }

    float *xr, *wqkvr, *wprojr, *attp;
    cudaGetSymbolAddress((void**)&xr, g_xr);
    cudaGetSymbolAddress((void**)&wqkvr, g_wqkvr);
    cudaGetSymbolAddress((void**)&wprojr, g_wprojr);
    cudaGetSymbolAddress((void**)&attp, g_att);

    // 0) Rounding prep (tf32 RNA), one launch: 2097152 f4 / 256 = 8192 blocks
    round_all<<<8192, 256>>>(x, w_qkv, w_proj);

    // 1) QKV projection -> rounded q/k/v in [B,H,T,D]
    mma_gemm<0, 3 * E_, E_><<<dim3(3 * E_ / BN, BT_ / BM), 128, GSMEM>>>(xr, wqkvr, nullptr);

    // 2) Causal flash attention -> rounded g_att [B*T, E]
    attn_mma<<<dim3(T_ / AQB, B_ * H_), 256, ASMEM>>>();

    // 3) Output projection -> d_out (fp32)
    mma_gemm<1, E_, E_><<<dim3(E_ / BN, BT_ / BM), 128, GSMEM>>>(attp, wprojr, out);
}